// round 6
// baseline (speedup 1.0000x reference)
#include <cuda_runtime.h>

#define NCLS 256

// ---------------------------------------------------------------------------
// Compile-time closed-form Cholesky factors of C0 = (K+0.001)*I - 11^T:
//   L0[j,j] = d_j, L0[i,j] = c_j (i > j)  [column-constant below diagonal]
//   u_j = g*(g-1-j)/(g-j), d_j = sqrt(u_j), c_j = -sqrt(g/((g-j)*(g-1-j)))
// with g = fp32-rounded (K + 0.001), matching the reference's fp32 C0.
// ---------------------------------------------------------------------------
struct Tbl { float c[NCLS]; float d[NCLS]; };

__host__ __device__ constexpr double csqrt_(double x) {
    double r = x > 1.0 ? x : 1.0;
    for (int i = 0; i < 50; ++i) r = 0.5 * (r + x / r);
    return r;
}

__host__ __device__ constexpr Tbl make_tbl_() {
    Tbl t{};
    const double g = (double)256.001f;   // fp32(K + 0.001), matches reference C0
    for (int j = 0; j < NCLS; ++j) {
        double a = g - (double)j;        // g - j
        double b = a - 1.0;              // g - 1 - j
        t.d[j] = (float)csqrt_(g * b / a);
        t.c[j] = (float)(-csqrt_(g / (a * b)));
    }
    return t;
}

__device__ const Tbl g_tbl = make_tbl_();

// ---------------------------------------------------------------------------
// One warp per TWO (b,s) rows (interleaved for ILP). Lane owns 8 contiguous
// classes of each row. Matvec with L0 collapses to a weighted prefix sum:
//   y_j = sum_{k<j} c_k*n_k + d_j*n_j
// Softmax uses the online (m,s) merge tree: local exps first, then ONE
// 5-level combine instead of separate max + sum trees.
// ---------------------------------------------------------------------------
__global__ __launch_bounds__(256, 5) void dbf_kernel(
    const int* __restrict__ data, const float* __restrict__ t,
    const float* __restrict__ noise, float* __restrict__ out, int rows)
{
    int warp = (int)((blockIdx.x * blockDim.x + threadIdx.x) >> 5);
    int lane = threadIdx.x & 31;
    int r0 = warp * 2;
    if (r0 >= rows) return;
    int r1 = (r0 + 1 < rows) ? (r0 + 1) : r0;   // rows is even in practice

    // Per-row scalars
    float tv[2]; tv[0] = __ldg(t + r0); tv[1] = __ldg(t + r1);
    int   xx[2]; xx[0] = __ldg(data + r0); xx[1] = __ldg(data + r1);
    float sb[2], beta[2]; bool lo[2];
#pragma unroll
    for (int r = 0; r < 2; r++) {
        float s = fminf(tv[r], 1.0f - 1e-6f);
        lo[r] = s < 1e-10f;
        s = fmaxf(s, 1e-10f);
        sb[r] = s;
        beta[r] = s * s;
    }

    // Table (c, d) for this lane's 8 classes (LDG, L1-resident)
    float4 ca = ((const float4*)g_tbl.c)[lane * 2];
    float4 cb = ((const float4*)g_tbl.c)[lane * 2 + 1];
    float4 da = ((const float4*)g_tbl.d)[lane * 2];
    float4 db = ((const float4*)g_tbl.d)[lane * 2 + 1];
    float c[8] = {ca.x, ca.y, ca.z, ca.w, cb.x, cb.y, cb.z, cb.w};
    float d[8] = {da.x, da.y, da.z, da.w, db.x, db.y, db.z, db.w};

    // Noise for both rows (2x float4 each, front-batched for MLP)
    const float4* np0 = (const float4*)noise + (size_t)r0 * (NCLS / 4) + lane * 2;
    const float4* np1 = (const float4*)noise + (size_t)r1 * (NCLS / 4) + lane * 2;
    float4 n0a = np0[0], n0b = np0[1];
    float4 n1a = np1[0], n1b = np1[1];
    float n[2][8] = {
        {n0a.x, n0a.y, n0a.z, n0a.w, n0b.x, n0b.y, n0b.z, n0b.w},
        {n1a.x, n1a.y, n1a.z, n1a.w, n1b.x, n1b.y, n1b.z, n1b.w}
    };

    // Thread-local total of c_j * n_j (prefix recomputed later — saves 16 regs)
    float acc[2] = {0.0f, 0.0f};
#pragma unroll
    for (int i = 0; i < 8; i++) {
#pragma unroll
        for (int r = 0; r < 2; r++) acc[r] = fmaf(c[i], n[r][i], acc[r]);
    }

    // Warp exclusive scan of per-thread totals (two chains interleaved)
    float sc0 = acc[0], sc1 = acc[1];
#pragma unroll
    for (int o = 1; o < 32; o <<= 1) {
        float v0 = __shfl_up_sync(0xffffffffu, sc0, o);
        float v1 = __shfl_up_sync(0xffffffffu, sc1, o);
        if (lane >= o) { sc0 += v0; sc1 += v1; }
    }
    float excl[2] = {sc0 - acc[0], sc1 - acc[1]};

    // logits_j = beta*(256*[j==x] - 1) + sqrt(beta)*(prefix_j + d_j*n_j)
    // (local prefix recomputed on the fly; logits overwrite n in place)
    int jbase = lane * 8;
    float Mloc[2] = {-1e30f, -1e30f};
#pragma unroll
    for (int r = 0; r < 2; r++) {
        float a = excl[r];
#pragma unroll
        for (int i = 0; i < 8; i++) {
            float ni = n[r][i];
            float y  = a + d[i] * ni;
            a = fmaf(c[i], ni, a);
            float m = (jbase + i == xx[r]) ? 256.0f * beta[r] : 0.0f;
            float l = (m - beta[r]) + sb[r] * y;
            n[r][i] = l;
            Mloc[r] = fmaxf(Mloc[r], l);
        }
    }

    // Local exps + sums (no shuffle wait needed — Mloc is thread-local)
    float s0 = 0.0f, s1 = 0.0f;
#pragma unroll
    for (int i = 0; i < 8; i++) {
        n[0][i] = __expf(n[0][i] - Mloc[0]); s0 += n[0][i];
        n[1][i] = __expf(n[1][i] - Mloc[1]); s1 += n[1][i];
    }

    // Online-softmax merge tree over (m, s), both rows interleaved
    float m0 = Mloc[0], m1 = Mloc[1];
#pragma unroll
    for (int o = 16; o > 0; o >>= 1) {
        float mo0 = __shfl_xor_sync(0xffffffffu, m0, o);
        float mo1 = __shfl_xor_sync(0xffffffffu, m1, o);
        float so0 = __shfl_xor_sync(0xffffffffu, s0, o);
        float so1 = __shfl_xor_sync(0xffffffffu, s1, o);
        float nm0 = fmaxf(m0, mo0);
        float nm1 = fmaxf(m1, mo1);
        s0 = fmaf(s0, __expf(m0 - nm0), so0 * __expf(mo0 - nm0));
        s1 = fmaf(s1, __expf(m1 - nm1), so1 * __expf(mo1 - nm1));
        m0 = nm0; m1 = nm1;
    }

    // p_i = e_i * exp(Mloc - M) / S   (or uniform 1/K for lo_beta rows)
    float sc_a = lo[0] ? 0.0f : __fdividef(__expf(Mloc[0] - m0), s0);
    float sc_b = lo[1] ? 0.0f : __fdividef(__expf(Mloc[1] - m1), s1);
    float add_a = lo[0] ? (1.0f / 256.0f) : 0.0f;
    float add_b = lo[1] ? (1.0f / 256.0f) : 0.0f;
#pragma unroll
    for (int i = 0; i < 8; i++) {
        n[0][i] = fmaf(n[0][i], sc_a, add_a);
        n[1][i] = fmaf(n[1][i], sc_b, add_b);
    }

    float4* op0 = (float4*)out + (size_t)r0 * (NCLS / 4) + lane * 2;
    float4* op1 = (float4*)out + (size_t)r1 * (NCLS / 4) + lane * 2;
    op0[0] = make_float4(n[0][0], n[0][1], n[0][2], n[0][3]);
    op0[1] = make_float4(n[0][4], n[0][5], n[0][6], n[0][7]);
    op1[0] = make_float4(n[1][0], n[1][1], n[1][2], n[1][3]);
    op1[1] = make_float4(n[1][4], n[1][5], n[1][6], n[1][7]);
}

extern "C" void kernel_launch(void* const* d_in, const int* in_sizes, int n_in,
                              void* d_out, int out_size) {
    const int*   data  = (const int*)d_in[0];
    const float* t     = (const float*)d_in[1];
    const float* noise = (const float*)d_in[2];
    float*       out   = (float*)d_out;
    int rows = in_sizes[1];                 // B*S = 16384

    int warps  = (rows + 1) / 2;            // 2 rows per warp
    int blocks = (warps + 7) / 8;           // 8 warps per block
    dbf_kernel<<<blocks, 256>>>(data, t, noise, out, rows);
}

// round 10
// speedup vs baseline: 1.1701x; 1.1701x over previous
#include <cuda_runtime.h>

#define NCLS 256

// ---------------------------------------------------------------------------
// Compile-time closed-form Cholesky factors of C0 = (K+0.001)*I - 11^T:
//   L0[j,j] = d_j, L0[i,j] = c_j (i > j)  [column-constant below diagonal]
//   u_j = g*(g-1-j)/(g-j), d_j = sqrt(u_j), c_j = -sqrt(g/((g-j)*(g-1-j)))
// with g = fp32-rounded (K + 0.001), matching the reference's fp32 C0.
// ---------------------------------------------------------------------------
struct Tbl { float c[NCLS]; float d[NCLS]; };

__host__ __device__ constexpr double csqrt_(double x) {
    double r = x > 1.0 ? x : 1.0;
    for (int i = 0; i < 50; ++i) r = 0.5 * (r + x / r);
    return r;
}

__host__ __device__ constexpr Tbl make_tbl_() {
    Tbl t{};
    const double g = (double)256.001f;   // fp32(K + 0.001), matches reference C0
    for (int j = 0; j < NCLS; ++j) {
        double a = g - (double)j;        // g - j
        double b = a - 1.0;              // g - 1 - j
        t.d[j] = (float)csqrt_(g * b / a);
        t.c[j] = (float)(-csqrt_(g / (a * b)));
    }
    return t;
}

__device__ const Tbl g_tbl = make_tbl_();

// ---------------------------------------------------------------------------
// One warp per TWO (b,s) rows (interleaved for ILP). Lane owns 8 contiguous
// classes of each row. Matvec with L0 collapses to a weighted prefix sum:
//   y_j = sum_{k<j} c_k*n_k + d_j*n_j
// Softmax: plain max-tree -> local exps -> sum-tree (MUFUs stay OUT of the
// serial shuffle chains). Local prefix recomputed to save 16 registers.
// ---------------------------------------------------------------------------
__global__ __launch_bounds__(256, 5) void dbf_kernel(
    const int* __restrict__ data, const float* __restrict__ t,
    const float* __restrict__ noise, float* __restrict__ out, int rows)
{
    int warp = (int)((blockIdx.x * blockDim.x + threadIdx.x) >> 5);
    int lane = threadIdx.x & 31;
    int r0 = warp * 2;
    if (r0 >= rows) return;
    int r1 = (r0 + 1 < rows) ? (r0 + 1) : r0;   // rows is even in practice

    // Per-row scalars
    float tv[2]; tv[0] = __ldg(t + r0); tv[1] = __ldg(t + r1);
    int   xx[2]; xx[0] = __ldg(data + r0); xx[1] = __ldg(data + r1);
    float sb[2], beta[2]; bool lo[2];
#pragma unroll
    for (int r = 0; r < 2; r++) {
        float s = fminf(tv[r], 1.0f - 1e-6f);
        lo[r] = s < 1e-10f;
        s = fmaxf(s, 1e-10f);
        sb[r] = s;
        beta[r] = s * s;
    }

    // Table (c, d) for this lane's 8 classes (LDG, L1-resident)
    float4 ca = ((const float4*)g_tbl.c)[lane * 2];
    float4 cb = ((const float4*)g_tbl.c)[lane * 2 + 1];
    float4 da = ((const float4*)g_tbl.d)[lane * 2];
    float4 db = ((const float4*)g_tbl.d)[lane * 2 + 1];
    float c[8] = {ca.x, ca.y, ca.z, ca.w, cb.x, cb.y, cb.z, cb.w};
    float d[8] = {da.x, da.y, da.z, da.w, db.x, db.y, db.z, db.w};

    // Noise for both rows (2x float4 each, front-batched for MLP)
    const float4* np0 = (const float4*)noise + (size_t)r0 * (NCLS / 4) + lane * 2;
    const float4* np1 = (const float4*)noise + (size_t)r1 * (NCLS / 4) + lane * 2;
    float4 n0a = np0[0], n0b = np0[1];
    float4 n1a = np1[0], n1b = np1[1];
    float n[2][8] = {
        {n0a.x, n0a.y, n0a.z, n0a.w, n0b.x, n0b.y, n0b.z, n0b.w},
        {n1a.x, n1a.y, n1a.z, n1a.w, n1b.x, n1b.y, n1b.z, n1b.w}
    };

    // Thread-local total of c_j * n_j (prefix recomputed later — saves regs)
    float acc[2] = {0.0f, 0.0f};
#pragma unroll
    for (int i = 0; i < 8; i++) {
#pragma unroll
        for (int r = 0; r < 2; r++) acc[r] = fmaf(c[i], n[r][i], acc[r]);
    }

    // Warp exclusive scan of per-thread totals (two chains interleaved)
    float sc0 = acc[0], sc1 = acc[1];
#pragma unroll
    for (int o = 1; o < 32; o <<= 1) {
        float v0 = __shfl_up_sync(0xffffffffu, sc0, o);
        float v1 = __shfl_up_sync(0xffffffffu, sc1, o);
        if (lane >= o) { sc0 += v0; sc1 += v1; }
    }
    float excl[2] = {sc0 - acc[0], sc1 - acc[1]};

    // logits_j = beta*(256*[j==x] - 1) + sqrt(beta)*(prefix_j + d_j*n_j)
    // (local prefix recomputed on the fly; logits overwrite n in place;
    //  both rows interleaved so the two 8-FMA prefix chains overlap)
    int jbase = lane * 8;
    float a0 = excl[0], a1 = excl[1];
    float mx0 = -1e30f, mx1 = -1e30f;
#pragma unroll
    for (int i = 0; i < 8; i++) {
        float ni0 = n[0][i], ni1 = n[1][i];
        float y0 = a0 + d[i] * ni0;
        float y1 = a1 + d[i] * ni1;
        a0 = fmaf(c[i], ni0, a0);
        a1 = fmaf(c[i], ni1, a1);
        float m0 = (jbase + i == xx[0]) ? 256.0f * beta[0] : 0.0f;
        float m1 = (jbase + i == xx[1]) ? 256.0f * beta[1] : 0.0f;
        float l0 = (m0 - beta[0]) + sb[0] * y0;
        float l1 = (m1 - beta[1]) + sb[1] * y1;
        n[0][i] = l0; n[1][i] = l1;
        mx0 = fmaxf(mx0, l0); mx1 = fmaxf(mx1, l1);
    }

    // Warp max trees (interleaved; ALU-only)
#pragma unroll
    for (int o = 16; o > 0; o >>= 1) {
        float v0 = __shfl_xor_sync(0xffffffffu, mx0, o);
        float v1 = __shfl_xor_sync(0xffffffffu, mx1, o);
        mx0 = fmaxf(mx0, v0); mx1 = fmaxf(mx1, v1);
    }

    // Local exps + sums (all 16 MUFUs independent, out of the shuffle chain)
    float s0 = 0.0f, s1 = 0.0f;
#pragma unroll
    for (int i = 0; i < 8; i++) {
        n[0][i] = __expf(n[0][i] - mx0); s0 += n[0][i];
        n[1][i] = __expf(n[1][i] - mx1); s1 += n[1][i];
    }

    // Warp sum trees (interleaved; ALU-only)
#pragma unroll
    for (int o = 16; o > 0; o >>= 1) {
        s0 += __shfl_xor_sync(0xffffffffu, s0, o);
        s1 += __shfl_xor_sync(0xffffffffu, s1, o);
    }

    // p = e / S, or uniform 1/K for lo_beta rows
    float sc_a = lo[0] ? 0.0f : __fdividef(1.0f, s0);
    float sc_b = lo[1] ? 0.0f : __fdividef(1.0f, s1);
    float add_a = lo[0] ? (1.0f / 256.0f) : 0.0f;
    float add_b = lo[1] ? (1.0f / 256.0f) : 0.0f;
#pragma unroll
    for (int i = 0; i < 8; i++) {
        n[0][i] = fmaf(n[0][i], sc_a, add_a);
        n[1][i] = fmaf(n[1][i], sc_b, add_b);
    }

    float4* op0 = (float4*)out + (size_t)r0 * (NCLS / 4) + lane * 2;
    float4* op1 = (float4*)out + (size_t)r1 * (NCLS / 4) + lane * 2;
    op0[0] = make_float4(n[0][0], n[0][1], n[0][2], n[0][3]);
    op0[1] = make_float4(n[0][4], n[0][5], n[0][6], n[0][7]);
    op1[0] = make_float4(n[1][0], n[1][1], n[1][2], n[1][3]);
    op1[1] = make_float4(n[1][4], n[1][5], n[1][6], n[1][7]);
}

extern "C" void kernel_launch(void* const* d_in, const int* in_sizes, int n_in,
                              void* d_out, int out_size) {
    const int*   data  = (const int*)d_in[0];
    const float* t     = (const float*)d_in[1];
    const float* noise = (const float*)d_in[2];
    float*       out   = (float*)d_out;
    int rows = in_sizes[1];                 // B*S = 16384

    int warps  = (rows + 1) / 2;            // 2 rows per warp
    int blocks = (warps + 7) / 8;           // 8 warps per block
    dbf_kernel<<<blocks, 256>>>(data, t, noise, out, rows);
}